// round 15
// baseline (speedup 1.0000x reference)
#include <cuda_runtime.h>
#include <cuda_fp16.h>

// SNN: B=4096, T=256, I=7, H=64, O=8
// R14 (= R13 with the b1 name collision fixed): 2 independent batches PER
// WARP (full 32-lane mapping each; 2 hidden units/lane/batch) to double
// per-warp ILP — single resident wave means duration == per-warp serial
// time, and interleaving two recurrences fills dependency-stall holes.
// Outputs via HMMA m16n8k16 (spikes exact fp16, W2 hi+lo split).

#define THRESH 1.0f
#define BETA 0.8f

typedef unsigned long long u64;
typedef unsigned int u32;

constexpr int T_ = 256;
constexpr int I_ = 7;
constexpr int H_ = 64;
constexpr int O_ = 8;
constexpr int WPB = 4;
constexpr int TCHUNK = 32;
constexpr int SPK_STRIDE = 72;   // halves per spike row (64 + 8 pad) = 144B

__device__ __forceinline__ u64 pack2(float lo, float hi) {
    u64 r; asm("mov.b64 %0, {%1, %2};" : "=l"(r) : "f"(lo), "f"(hi)); return r;
}
__device__ __forceinline__ void unpack2(u64 v, float& lo, float& hi) {
    asm("mov.b64 {%0, %1}, %2;" : "=f"(lo), "=f"(hi) : "l"(v));
}
__device__ __forceinline__ u64 fma2(u64 a, u64 b, u64 c) {
    u64 d; asm("fma.rn.f32x2 %0, %1, %2, %3;" : "=l"(d) : "l"(a), "l"(b), "l"(c)); return d;
}
__device__ __forceinline__ u32 cvt_f16x2(float lo, float hi) {
    u32 r; asm("cvt.rn.f16x2.f32 %0, %1, %2;" : "=r"(r) : "f"(hi), "f"(lo)); return r;
}
__device__ __forceinline__ void ldsm_x4(u32& r0, u32& r1, u32& r2, u32& r3, u32 addr) {
    asm volatile("ldmatrix.sync.aligned.m8n8.x4.shared.b16 {%0,%1,%2,%3}, [%4];"
                 : "=r"(r0), "=r"(r1), "=r"(r2), "=r"(r3) : "r"(addr));
}
__device__ __forceinline__ void mma16816(float& c0, float& c1, float& c2, float& c3,
                                         u32 a0, u32 a1, u32 a2, u32 a3,
                                         u32 b0, u32 b1) {
    asm volatile("mma.sync.aligned.m16n8k16.row.col.f32.f16.f16.f32 "
                 "{%0,%1,%2,%3},{%4,%5,%6,%7},{%8,%9},{%0,%1,%2,%3};"
                 : "+f"(c0), "+f"(c1), "+f"(c2), "+f"(c3)
                 : "r"(a0), "r"(a1), "r"(a2), "r"(a3), "r"(b0), "r"(b1));
}

__global__ __launch_bounds__(WPB * 32, 4)
void snn_kernel(const float* __restrict__ x,
                const float* __restrict__ hs,
                const float* __restrict__ W1,
                const float* __restrict__ b1,
                const float* __restrict__ W2,
                const float* __restrict__ b2,
                float* __restrict__ out,     // (B,T,8)
                float* __restrict__ newh,    // (B,T,64)
                int B)
{
    // Per warp: 2 batches. x staged padded to 8 floats/step per batch.
    __shared__ __align__(16) u64 xs[WPB][2][TCHUNK * 4];                     // 8 KB
    __shared__ __align__(16) unsigned short spk[WPB][2][TCHUNK][SPK_STRIDE]; // 36 KB

    const int w    = threadIdx.x >> 5;
    const int lane = threadIdx.x & 31;
    const int gw   = blockIdx.x * WPB + w;
    const int bA   = 2 * gw;
    const int bB   = 2 * gw + 1;
    if (bA >= B) return;

    const int h0 = 2 * lane;
    const int kp = 2 * (lane & 3);

    // --- W1 packed over input pairs (shared by both batches) ---
    u64 w1a[4], w1b[4];
#pragma unroll
    for (int k = 0; k < 3; k++) {
        w1a[k] = pack2(W1[h0 * I_ + 2 * k],       W1[h0 * I_ + 2 * k + 1]);
        w1b[k] = pack2(W1[(h0 + 1) * I_ + 2 * k], W1[(h0 + 1) * I_ + 2 * k + 1]);
    }
    w1a[3] = pack2(W1[h0 * I_ + 6], 0.0f);
    w1b[3] = pack2(W1[(h0 + 1) * I_ + 6], 0.0f);
    const u64 bias1a = pack2(b1[h0], 0.0f);
    const u64 bias1b = pack2(b1[h0 + 1], 0.0f);

    // --- W2 B-fragments (n8k16 col-major), hi+lo fp16 split (shared) ---
    u32 bhi[4][2], blo[4][2];
    {
        const int o = lane >> 2;
#pragma unroll
        for (int kt = 0; kt < 4; kt++) {
#pragma unroll
            for (int half = 0; half < 2; half++) {
                const int k = kt * 16 + half * 8 + kp;
                float wa = W2[o * H_ + k], wb = W2[o * H_ + k + 1];
                __half ha = __float2half_rn(wa);
                __half hb = __float2half_rn(wb);
                __half la = __float2half_rn(wa - __half2float(ha));
                __half lb = __float2half_rn(wb - __half2float(hb));
                __half2 vh = __halves2half2(ha, hb);
                __half2 vl = __halves2half2(la, lb);
                bhi[kt][half] = *reinterpret_cast<u32*>(&vh);
                blo[kt][half] = *reinterpret_cast<u32*>(&vl);
            }
        }
    }
    const float bi0 = b2[kp];
    const float bi1 = b2[kp + 1];

    // --- initial membranes + initial resets (both batches) ---
    float memA0, memA1, memB0, memB1, sA0, sA1, sB0, sB1;
    {
        const float2 mA = *reinterpret_cast<const float2*>(hs + (size_t)bA * H_ + h0);
        const float2 mB = *reinterpret_cast<const float2*>(hs + (size_t)bB * H_ + h0);
        memA0 = mA.x; memA1 = mA.y; memB0 = mB.x; memB1 = mB.y;
        sA0 = (float)(memA0 > THRESH); sA1 = (float)(memA1 > THRESH);
        sB0 = (float)(memB0 > THRESH); sB1 = (float)(memB1 > THRESH);
    }

    const float* xbA = x    + (size_t)bA * T_ * I_;
    const float* xbB = x    + (size_t)bB * T_ * I_;
    float*       nhA = newh + (size_t)bA * T_ * H_ + h0;
    float*       nhB = newh + (size_t)bB * T_ * H_ + h0;
    float*       obA = out  + (size_t)bA * T_ * O_;
    float*       obB = out  + (size_t)bB * T_ * O_;

    const u32 sbase0 = (u32)__cvta_generic_to_shared(&spk[w][0][0][0]);
    const u32 sbase1 = (u32)__cvta_generic_to_shared(&spk[w][1][0][0]);
    const u32 lm_off = (u32)(lane & 15) * (SPK_STRIDE * 2) + (u32)(lane >> 4) * 16;

    for (int c0 = 0; c0 < T_; c0 += TCHUNK) {
        // ---- stage x chunks for both batches (lane = timestep) ----
#pragma unroll
        for (int bb = 0; bb < 2; bb++) {
            const float* src = (bb ? xbB : xbA) + (size_t)(c0 + lane) * I_;
            float v0 = __ldcs(src + 0), v1 = __ldcs(src + 1);
            float v2 = __ldcs(src + 2), v3 = __ldcs(src + 3);
            float v4 = __ldcs(src + 4), v5 = __ldcs(src + 5);
            float v6 = __ldcs(src + 6);
            ulonglong2 lo, hi;
            lo.x = pack2(v0, v1); lo.y = pack2(v2, v3);
            hi.x = pack2(v4, v5); hi.y = pack2(v6, 0.0f);
            *reinterpret_cast<ulonglong2*>(&xs[w][bb][lane * 4])     = lo;
            *reinterpret_cast<ulonglong2*>(&xs[w][bb][lane * 4 + 2]) = hi;
        }
        __syncwarp();

        // ---- phase 1: two interleaved recurrences over 32 steps ----
#pragma unroll 4
        for (int tt = 0; tt < TCHUNK; tt++) {
            const int t = c0 + tt;
            const ulonglong2 xloA = *reinterpret_cast<const ulonglong2*>(&xs[w][0][tt * 4]);
            const ulonglong2 xhiA = *reinterpret_cast<const ulonglong2*>(&xs[w][0][tt * 4 + 2]);
            const ulonglong2 xloB = *reinterpret_cast<const ulonglong2*>(&xs[w][1][tt * 4]);
            const ulonglong2 xhiB = *reinterpret_cast<const ulonglong2*>(&xs[w][1][tt * 4 + 2]);

            u64 aaA = fma2(xloA.x, w1a[0], fma2(xloA.y, w1a[1],
                      fma2(xhiA.x, w1a[2], fma2(xhiA.y, w1a[3], bias1a))));
            u64 abA = fma2(xloA.x, w1b[0], fma2(xloA.y, w1b[1],
                      fma2(xhiA.x, w1b[2], fma2(xhiA.y, w1b[3], bias1b))));
            u64 aaB = fma2(xloB.x, w1a[0], fma2(xloB.y, w1a[1],
                      fma2(xhiB.x, w1a[2], fma2(xhiB.y, w1a[3], bias1a))));
            u64 abB = fma2(xloB.x, w1b[0], fma2(xloB.y, w1b[1],
                      fma2(xhiB.x, w1b[2], fma2(xhiB.y, w1b[3], bias1b))));

            float u0, u1, cA0, cA1, cB0, cB1;
            unpack2(aaA, u0, u1); cA0 = u0 + u1;
            unpack2(abA, u0, u1); cA1 = u0 + u1;
            unpack2(aaB, u0, u1); cB0 = u0 + u1;
            unpack2(abB, u0, u1); cB1 = u0 + u1;

            memA0 = fmaf(BETA, memA0, cA0) - sA0;
            memA1 = fmaf(BETA, memA1, cA1) - sA1;
            memB0 = fmaf(BETA, memB0, cB0) - sB0;
            memB1 = fmaf(BETA, memB1, cB1) - sB1;

            __stcs(reinterpret_cast<float2*>(nhA + (size_t)t * H_),
                   make_float2(memA0, memA1));
            __stcs(reinterpret_cast<float2*>(nhB + (size_t)t * H_),
                   make_float2(memB0, memB1));

            sA0 = (float)(memA0 > THRESH);
            sA1 = (float)(memA1 > THRESH);
            sB0 = (float)(memB0 > THRESH);
            sB1 = (float)(memB1 > THRESH);

            *reinterpret_cast<u32*>(&spk[w][0][tt][h0]) = cvt_f16x2(sA0, sA1);
            *reinterpret_cast<u32*>(&spk[w][1][tt][h0]) = cvt_f16x2(sB0, sB1);
        }
        __syncwarp();

        // ---- phase 2: outputs for both batches via HMMA ----
#pragma unroll
        for (int bb = 0; bb < 2; bb++) {
            const u32 base = (bb ? sbase1 : sbase0) + lm_off;
            float* obp = bb ? obB : obA;
#pragma unroll
            for (int mt = 0; mt < 2; mt++) {
                float d0 = bi0, d1 = bi1, d2 = bi0, d3 = bi1;
#pragma unroll
                for (int kt = 0; kt < 4; kt++) {
                    u32 a0, a1, a2, a3;
                    ldsm_x4(a0, a1, a2, a3,
                            base + (u32)(mt * 16 * SPK_STRIDE * 2) + (u32)(kt * 32));
                    mma16816(d0, d1, d2, d3, a0, a1, a2, a3, bhi[kt][0], bhi[kt][1]);
                    mma16816(d0, d1, d2, d3, a0, a1, a2, a3, blo[kt][0], blo[kt][1]);
                }
                const int row = mt * 16 + (lane >> 2);
                __stcs(reinterpret_cast<float2*>(obp + (size_t)(c0 + row) * O_ + kp),
                       make_float2(d0, d1));
                __stcs(reinterpret_cast<float2*>(obp + (size_t)(c0 + row + 8) * O_ + kp),
                       make_float2(d2, d3));
            }
        }
        __syncwarp();
    }
}

extern "C" void kernel_launch(void* const* d_in, const int* in_sizes, int n_in,
                              void* d_out, int out_size)
{
    const float* x  = (const float*)d_in[0];
    const float* hs = (const float*)d_in[1];
    const float* W1 = (const float*)d_in[2];
    const float* b1 = (const float*)d_in[3];
    const float* W2 = (const float*)d_in[4];
    const float* b2 = (const float*)d_in[5];

    const int B = in_sizes[1] / H_;

    float* out  = (float*)d_out;                       // (B,T,O)
    float* newh = (float*)d_out + (size_t)B * T_ * O_; // (B,T,H)

    const int warps  = B / 2;                 // 2 batches per warp
    const int blocks = (warps + WPB - 1) / WPB;
    snn_kernel<<<blocks, WPB * 32>>>(x, hs, W1, b1, W2, b2, out, newh, B);
}

// round 16
// speedup vs baseline: 1.0291x; 1.0291x over previous
#include <cuda_runtime.h>
#include <cuda_fp16.h>

// SNN: B=4096, T=256, I=7, H=64, O=8
// R15 = R9 (best) with write-through stores for the 301MB output stream.
// Theory: duration equals write-bytes / effective-write-BW (R8 proved store
// decoupling doesn't change time). st.global.wt avoids L2 dirty-eviction
// handling for never-re-read lines; if LTS eviction is the floor, this lifts it.

#define THRESH 1.0f
#define BETA 0.8f

typedef unsigned long long u64;
typedef unsigned int u32;

constexpr int T_ = 256;
constexpr int I_ = 7;
constexpr int H_ = 64;
constexpr int O_ = 8;
constexpr int WPB = 4;
constexpr int TCHUNK = 32;
constexpr int SPK_STRIDE = 72;   // halves per spike row (64 + 8 pad) = 144B

__device__ __forceinline__ u64 pack2(float lo, float hi) {
    u64 r; asm("mov.b64 %0, {%1, %2};" : "=l"(r) : "f"(lo), "f"(hi)); return r;
}
__device__ __forceinline__ void unpack2(u64 v, float& lo, float& hi) {
    asm("mov.b64 {%0, %1}, %2;" : "=f"(lo), "=f"(hi) : "l"(v));
}
__device__ __forceinline__ u64 fma2(u64 a, u64 b, u64 c) {
    u64 d; asm("fma.rn.f32x2 %0, %1, %2, %3;" : "=l"(d) : "l"(a), "l"(b), "l"(c)); return d;
}
__device__ __forceinline__ u32 cvt_f16x2(float lo, float hi) {
    u32 r; asm("cvt.rn.f16x2.f32 %0, %1, %2;" : "=r"(r) : "f"(hi), "f"(lo)); return r;
}
__device__ __forceinline__ void stwt_f2(float* p, float a, float b) {
    asm volatile("st.global.wt.v2.f32 [%0], {%1, %2};"
                 :: "l"(p), "f"(a), "f"(b) : "memory");
}
__device__ __forceinline__ void ldsm_x4(u32& r0, u32& r1, u32& r2, u32& r3, u32 addr) {
    asm volatile("ldmatrix.sync.aligned.m8n8.x4.shared.b16 {%0,%1,%2,%3}, [%4];"
                 : "=r"(r0), "=r"(r1), "=r"(r2), "=r"(r3) : "r"(addr));
}
__device__ __forceinline__ void mma16816(float& c0, float& c1, float& c2, float& c3,
                                         u32 a0, u32 a1, u32 a2, u32 a3,
                                         u32 b0, u32 b1) {
    asm volatile("mma.sync.aligned.m16n8k16.row.col.f32.f16.f16.f32 "
                 "{%0,%1,%2,%3},{%4,%5,%6,%7},{%8,%9},{%0,%1,%2,%3};"
                 : "+f"(c0), "+f"(c1), "+f"(c2), "+f"(c3)
                 : "r"(a0), "r"(a1), "r"(a2), "r"(a3), "r"(b0), "r"(b1));
}

__global__ __launch_bounds__(WPB * 32, 8)
void snn_kernel(const float* __restrict__ x,
                const float* __restrict__ hs,
                const float* __restrict__ W1,
                const float* __restrict__ b1,
                const float* __restrict__ W2,
                const float* __restrict__ b2,
                float* __restrict__ out,     // (B,T,8)
                float* __restrict__ newh,    // (B,T,64)
                int B)
{
    // x staged plain, 8 floats (4 pairs) per timestep: u64[4] per step.
    __shared__ __align__(16) u64 xs[WPB][TCHUNK * 4];       // 4 KB
    __shared__ __align__(16) unsigned short spk[WPB][TCHUNK][SPK_STRIDE]; // 18 KB

    const int w    = threadIdx.x >> 5;
    const int lane = threadIdx.x & 31;
    const int b    = blockIdx.x * WPB + w;
    if (b >= B) return;

    const int h0 = 2 * lane;
    const int kp = 2 * (lane & 3);

    // --- W1 packed over input pairs (bias folded into accumulator init) ---
    u64 w1a[4], w1b[4];
#pragma unroll
    for (int k = 0; k < 3; k++) {
        w1a[k] = pack2(W1[h0 * I_ + 2 * k],       W1[h0 * I_ + 2 * k + 1]);
        w1b[k] = pack2(W1[(h0 + 1) * I_ + 2 * k], W1[(h0 + 1) * I_ + 2 * k + 1]);
    }
    w1a[3] = pack2(W1[h0 * I_ + 6], 0.0f);
    w1b[3] = pack2(W1[(h0 + 1) * I_ + 6], 0.0f);
    const u64 b1a = pack2(b1[h0], 0.0f);
    const u64 b1b = pack2(b1[h0 + 1], 0.0f);

    // --- B fragments for HMMA (n8k16 col-major), W2 hi+lo fp16 split ---
    u32 bhi[4][2], blo[4][2];
    {
        const int o = lane >> 2;
#pragma unroll
        for (int kt = 0; kt < 4; kt++) {
#pragma unroll
            for (int half = 0; half < 2; half++) {
                const int k = kt * 16 + half * 8 + kp;
                float wa = W2[o * H_ + k], wb = W2[o * H_ + k + 1];
                __half ha = __float2half_rn(wa);
                __half hb = __float2half_rn(wb);
                __half la = __float2half_rn(wa - __half2float(ha));
                __half lb = __float2half_rn(wb - __half2float(hb));
                __half2 vh = __halves2half2(ha, hb);
                __half2 vl = __halves2half2(la, lb);
                bhi[kt][half] = *reinterpret_cast<u32*>(&vh);
                blo[kt][half] = *reinterpret_cast<u32*>(&vl);
            }
        }
    }
    const float bi0 = b2[kp];
    const float bi1 = b2[kp + 1];

    // --- initial membrane + initial reset ---
    const float2 m2 = *reinterpret_cast<const float2*>(hs + (size_t)b * H_ + h0);
    float mem0 = m2.x, mem1 = m2.y;
    float s0 = (float)(mem0 > THRESH);
    float s1 = (float)(mem1 > THRESH);

    const float* xb = x    + (size_t)b * T_ * I_;
    float*       nh = newh + (size_t)b * T_ * H_ + h0;
    float*       ob = out  + (size_t)b * T_ * O_;

    const u32 spk_base = (u32)__cvta_generic_to_shared(&spk[w][0][0]);
    const u32 lm_addr0 = spk_base + (u32)(lane & 15) * (SPK_STRIDE * 2)
                                  + (u32)(lane >> 4) * 16;

    for (int c0 = 0; c0 < T_; c0 += TCHUNK) {
        // ---- stage x chunk: lane tt loads its timestep's 7 floats,
        //      writes 2 STS.128 (pads i=7 with 0) ----
        {
            const float* src = xb + (size_t)(c0 + lane) * I_;
            float v0 = __ldcs(src + 0), v1 = __ldcs(src + 1);
            float v2 = __ldcs(src + 2), v3 = __ldcs(src + 3);
            float v4 = __ldcs(src + 4), v5 = __ldcs(src + 5);
            float v6 = __ldcs(src + 6);
            ulonglong2 lo, hi;
            lo.x = pack2(v0, v1); lo.y = pack2(v2, v3);
            hi.x = pack2(v4, v5); hi.y = pack2(v6, 0.0f);
            *reinterpret_cast<ulonglong2*>(&xs[w][lane * 4])     = lo;
            *reinterpret_cast<ulonglong2*>(&xs[w][lane * 4 + 2]) = hi;
        }
        __syncwarp();

        // ---- phase 1: recurrence over 32 steps, chain = FFMA+FSUB only ----
#pragma unroll 8
        for (int tt = 0; tt < TCHUNK; tt++) {
            const int t = c0 + tt;
            const ulonglong2 xlo = *reinterpret_cast<const ulonglong2*>(&xs[w][tt * 4]);
            const ulonglong2 xhi = *reinterpret_cast<const ulonglong2*>(&xs[w][tt * 4 + 2]);

            // cur for h0 / h1: 4 FFMA2 each, packed over input pairs
            u64 aa = fma2(xlo.x, w1a[0],
                     fma2(xlo.y, w1a[1],
                     fma2(xhi.x, w1a[2],
                     fma2(xhi.y, w1a[3], b1a))));
            u64 ab = fma2(xlo.x, w1b[0],
                     fma2(xlo.y, w1b[1],
                     fma2(xhi.x, w1b[2],
                     fma2(xhi.y, w1b[3], b1b))));
            float a0, a1, c0f, c1f;
            unpack2(aa, a0, a1); c0f = a0 + a1;
            unpack2(ab, a0, a1); c1f = a0 + a1;

            // mem' = (BETA*mem + cur) - spike_prev ; spike via FSET (4 cyc)
            mem0 = fmaf(BETA, mem0, c0f) - s0;
            mem1 = fmaf(BETA, mem1, c1f) - s1;

            // write-through store: no L2 dirty-eviction handling
            stwt_f2(nh + (size_t)t * H_, mem0, mem1);

            s0 = (float)(mem0 > THRESH);
            s1 = (float)(mem1 > THRESH);

            *reinterpret_cast<u32*>(&spk[w][tt][h0]) = cvt_f16x2(s0, s1);
        }
        __syncwarp();

        // ---- phase 2: outputs for 32 steps via HMMA ----
#pragma unroll
        for (int mt = 0; mt < 2; mt++) {
            float d0 = bi0, d1 = bi1, d2 = bi0, d3 = bi1;
#pragma unroll
            for (int kt = 0; kt < 4; kt++) {
                u32 a0, a1, a2, a3;
                ldsm_x4(a0, a1, a2, a3,
                        lm_addr0 + (u32)(mt * 16 * SPK_STRIDE * 2) + (u32)(kt * 32));
                mma16816(d0, d1, d2, d3, a0, a1, a2, a3, bhi[kt][0], bhi[kt][1]);
                mma16816(d0, d1, d2, d3, a0, a1, a2, a3, blo[kt][0], blo[kt][1]);
            }
            const int row = mt * 16 + (lane >> 2);
            stwt_f2(ob + (size_t)(c0 + row) * O_ + kp, d0, d1);
            stwt_f2(ob + (size_t)(c0 + row + 8) * O_ + kp, d2, d3);
        }
        __syncwarp();
    }
}

extern "C" void kernel_launch(void* const* d_in, const int* in_sizes, int n_in,
                              void* d_out, int out_size)
{
    const float* x  = (const float*)d_in[0];
    const float* hs = (const float*)d_in[1];
    const float* W1 = (const float*)d_in[2];
    const float* b1 = (const float*)d_in[3];
    const float* W2 = (const float*)d_in[4];
    const float* b2 = (const float*)d_in[5];

    const int B = in_sizes[1] / H_;

    float* out  = (float*)d_out;                       // (B,T,O)
    float* newh = (float*)d_out + (size_t)B * T_ * O_; // (B,T,H)

    const int blocks = (B + WPB - 1) / WPB;
    snn_kernel<<<blocks, WPB * 32>>>(x, hs, W1, b1, W2, b2, out, newh, B);
}

// round 17
// speedup vs baseline: 1.0300x; 1.0008x over previous
#include <cuda_runtime.h>
#include <cuda_fp16.h>

// SNN: B=4096, T=256, I=7, H=64, O=8
// R16 = R9 (best ncu) + coalesced x staging: 2 LDG.128 into scratch
// (reused spike tile), conflict-free LDS.32 transpose (stride 7 coprime
// with 32 banks) into the padded per-step layout. x reads keep .cs so the
// streamed 29MB doesn't evict L2 write-buffer capacity (the binder is the
// sustained HBM write drain of the 301MB output stream).

#define THRESH 1.0f
#define BETA 0.8f

typedef unsigned long long u64;
typedef unsigned int u32;

constexpr int T_ = 256;
constexpr int I_ = 7;
constexpr int H_ = 64;
constexpr int O_ = 8;
constexpr int WPB = 4;
constexpr int TCHUNK = 32;
constexpr int SPK_STRIDE = 72;   // halves per spike row (64 + 8 pad) = 144B

__device__ __forceinline__ u64 pack2(float lo, float hi) {
    u64 r; asm("mov.b64 %0, {%1, %2};" : "=l"(r) : "f"(lo), "f"(hi)); return r;
}
__device__ __forceinline__ void unpack2(u64 v, float& lo, float& hi) {
    asm("mov.b64 {%0, %1}, %2;" : "=f"(lo), "=f"(hi) : "l"(v));
}
__device__ __forceinline__ u64 fma2(u64 a, u64 b, u64 c) {
    u64 d; asm("fma.rn.f32x2 %0, %1, %2, %3;" : "=l"(d) : "l"(a), "l"(b), "l"(c)); return d;
}
__device__ __forceinline__ u32 cvt_f16x2(float lo, float hi) {
    u32 r; asm("cvt.rn.f16x2.f32 %0, %1, %2;" : "=r"(r) : "f"(hi), "f"(lo)); return r;
}
__device__ __forceinline__ void ldsm_x4(u32& r0, u32& r1, u32& r2, u32& r3, u32 addr) {
    asm volatile("ldmatrix.sync.aligned.m8n8.x4.shared.b16 {%0,%1,%2,%3}, [%4];"
                 : "=r"(r0), "=r"(r1), "=r"(r2), "=r"(r3) : "r"(addr));
}
__device__ __forceinline__ void mma16816(float& c0, float& c1, float& c2, float& c3,
                                         u32 a0, u32 a1, u32 a2, u32 a3,
                                         u32 b0, u32 b1) {
    asm volatile("mma.sync.aligned.m16n8k16.row.col.f32.f16.f16.f32 "
                 "{%0,%1,%2,%3},{%4,%5,%6,%7},{%8,%9},{%0,%1,%2,%3};"
                 : "+f"(c0), "+f"(c1), "+f"(c2), "+f"(c3)
                 : "r"(a0), "r"(a1), "r"(a2), "r"(a3), "r"(b0), "r"(b1));
}

__global__ __launch_bounds__(WPB * 32, 8)
void snn_kernel(const float* __restrict__ x,
                const float* __restrict__ hs,
                const float* __restrict__ W1,
                const float* __restrict__ b1,
                const float* __restrict__ W2,
                const float* __restrict__ b2,
                float* __restrict__ out,     // (B,T,8)
                float* __restrict__ newh,    // (B,T,64)
                int B)
{
    // x staged plain, 8 floats (4 pairs) per timestep: u64[4] per step.
    __shared__ __align__(16) u64 xs[WPB][TCHUNK * 4];       // 4 KB
    __shared__ __align__(16) unsigned short spk[WPB][TCHUNK][SPK_STRIDE]; // 18 KB

    const int w    = threadIdx.x >> 5;
    const int lane = threadIdx.x & 31;
    const int b    = blockIdx.x * WPB + w;
    if (b >= B) return;

    const int h0 = 2 * lane;
    const int kp = 2 * (lane & 3);

    // --- W1 packed over input pairs (bias folded into accumulator init) ---
    u64 w1a[4], w1b[4];
#pragma unroll
    for (int k = 0; k < 3; k++) {
        w1a[k] = pack2(W1[h0 * I_ + 2 * k],       W1[h0 * I_ + 2 * k + 1]);
        w1b[k] = pack2(W1[(h0 + 1) * I_ + 2 * k], W1[(h0 + 1) * I_ + 2 * k + 1]);
    }
    w1a[3] = pack2(W1[h0 * I_ + 6], 0.0f);
    w1b[3] = pack2(W1[(h0 + 1) * I_ + 6], 0.0f);
    const u64 b1a = pack2(b1[h0], 0.0f);
    const u64 b1b = pack2(b1[h0 + 1], 0.0f);

    // --- B fragments for HMMA (n8k16 col-major), W2 hi+lo fp16 split ---
    u32 bhi[4][2], blo[4][2];
    {
        const int o = lane >> 2;
#pragma unroll
        for (int kt = 0; kt < 4; kt++) {
#pragma unroll
            for (int half = 0; half < 2; half++) {
                const int k = kt * 16 + half * 8 + kp;
                float wa = W2[o * H_ + k], wb = W2[o * H_ + k + 1];
                __half ha = __float2half_rn(wa);
                __half hb = __float2half_rn(wb);
                __half la = __float2half_rn(wa - __half2float(ha));
                __half lb = __float2half_rn(wb - __half2float(hb));
                __half2 vh = __halves2half2(ha, hb);
                __half2 vl = __halves2half2(la, lb);
                bhi[kt][half] = *reinterpret_cast<u32*>(&vh);
                blo[kt][half] = *reinterpret_cast<u32*>(&vl);
            }
        }
    }
    const float bi0 = b2[kp];
    const float bi1 = b2[kp + 1];

    // --- initial membrane + initial reset ---
    const float2 m2 = *reinterpret_cast<const float2*>(hs + (size_t)b * H_ + h0);
    float mem0 = m2.x, mem1 = m2.y;
    float s0 = (float)(mem0 > THRESH);
    float s1 = (float)(mem1 > THRESH);

    const float* xb = x    + (size_t)b * T_ * I_;
    float*       nh = newh + (size_t)b * T_ * H_ + h0;
    float*       ob = out  + (size_t)b * T_ * O_;

    const u32 spk_base = (u32)__cvta_generic_to_shared(&spk[w][0][0]);
    const u32 lm_addr0 = spk_base + (u32)(lane & 15) * (SPK_STRIDE * 2)
                                  + (u32)(lane >> 4) * 16;

    for (int c0 = 0; c0 < T_; c0 += TCHUNK) {
        // ---- stage x chunk, fully coalesced ----
        // Step A: 56 float4 (224 floats) -> scratch (reuses spike tile,
        // which phase 2 of the previous chunk has finished reading).
        {
            float4* scratch = reinterpret_cast<float4*>(&spk[w][0][0]);
            const float4* src = reinterpret_cast<const float4*>(xb + (size_t)c0 * I_);
            scratch[lane] = __ldcs(&src[lane]);
            if (lane < 24) scratch[32 + lane] = __ldcs(&src[32 + lane]);
        }
        __syncwarp();
        // Step B: transpose to padded layout. Lane = timestep; reads 7
        // floats at stride-28B (7 words, coprime with 32 banks -> conflict
        // free), writes 2 STS.128.
        {
            const float* srow = reinterpret_cast<const float*>(&spk[w][0][0])
                                + lane * I_;
            const float v0 = srow[0], v1 = srow[1], v2 = srow[2], v3 = srow[3];
            const float v4 = srow[4], v5 = srow[5], v6 = srow[6];
            ulonglong2 lo, hi;
            lo.x = pack2(v0, v1); lo.y = pack2(v2, v3);
            hi.x = pack2(v4, v5); hi.y = pack2(v6, 0.0f);
            *reinterpret_cast<ulonglong2*>(&xs[w][lane * 4])     = lo;
            *reinterpret_cast<ulonglong2*>(&xs[w][lane * 4 + 2]) = hi;
        }
        __syncwarp();

        // ---- phase 1: recurrence over 32 steps, chain = FFMA+FSUB only ----
#pragma unroll 8
        for (int tt = 0; tt < TCHUNK; tt++) {
            const int t = c0 + tt;
            const ulonglong2 xlo = *reinterpret_cast<const ulonglong2*>(&xs[w][tt * 4]);
            const ulonglong2 xhi = *reinterpret_cast<const ulonglong2*>(&xs[w][tt * 4 + 2]);

            // cur for h0 / h1: 4 FFMA2 each, packed over input pairs
            u64 aa = fma2(xlo.x, w1a[0],
                     fma2(xlo.y, w1a[1],
                     fma2(xhi.x, w1a[2],
                     fma2(xhi.y, w1a[3], b1a))));
            u64 ab = fma2(xlo.x, w1b[0],
                     fma2(xlo.y, w1b[1],
                     fma2(xhi.x, w1b[2],
                     fma2(xhi.y, w1b[3], b1b))));
            float a0, a1, c0f, c1f;
            unpack2(aa, a0, a1); c0f = a0 + a1;
            unpack2(ab, a0, a1); c1f = a0 + a1;

            // mem' = (BETA*mem + cur) - spike_prev ; spike via FSET (4 cyc)
            mem0 = fmaf(BETA, mem0, c0f) - s0;
            mem1 = fmaf(BETA, mem1, c1f) - s1;

            __stcs(reinterpret_cast<float2*>(nh + (size_t)t * H_),
                   make_float2(mem0, mem1));

            s0 = (float)(mem0 > THRESH);
            s1 = (float)(mem1 > THRESH);

            *reinterpret_cast<u32*>(&spk[w][tt][h0]) = cvt_f16x2(s0, s1);
        }
        __syncwarp();

        // ---- phase 2: outputs for 32 steps via HMMA ----
#pragma unroll
        for (int mt = 0; mt < 2; mt++) {
            float d0 = bi0, d1 = bi1, d2 = bi0, d3 = bi1;
#pragma unroll
            for (int kt = 0; kt < 4; kt++) {
                u32 a0, a1, a2, a3;
                ldsm_x4(a0, a1, a2, a3,
                        lm_addr0 + (u32)(mt * 16 * SPK_STRIDE * 2) + (u32)(kt * 32));
                mma16816(d0, d1, d2, d3, a0, a1, a2, a3, bhi[kt][0], bhi[kt][1]);
                mma16816(d0, d1, d2, d3, a0, a1, a2, a3, blo[kt][0], blo[kt][1]);
            }
            const int row = mt * 16 + (lane >> 2);
            __stcs(reinterpret_cast<float2*>(ob + (size_t)(c0 + row) * O_ + kp),
                   make_float2(d0, d1));
            __stcs(reinterpret_cast<float2*>(ob + (size_t)(c0 + row + 8) * O_ + kp),
                   make_float2(d2, d3));
        }
        __syncwarp();
    }
}

extern "C" void kernel_launch(void* const* d_in, const int* in_sizes, int n_in,
                              void* d_out, int out_size)
{
    const float* x  = (const float*)d_in[0];
    const float* hs = (const float*)d_in[1];
    const float* W1 = (const float*)d_in[2];
    const float* b1 = (const float*)d_in[3];
    const float* W2 = (const float*)d_in[4];
    const float* b2 = (const float*)d_in[5];

    const int B = in_sizes[1] / H_;

    float* out  = (float*)d_out;                       // (B,T,O)
    float* newh = (float*)d_out + (size_t)B * T_ * O_; // (B,T,H)

    const int blocks = (B + WPB - 1) / WPB;
    snn_kernel<<<blocks, WPB * 32>>>(x, hs, W1, b1, W2, b2, out, newh, B);
}